// round 2
// baseline (speedup 1.0000x reference)
#include <cuda_runtime.h>

// Lorenz Taylor-step elementwise map.  (N,3) f32 -> (N,3) f32.
// Latency-bound fix: 8 rows/thread = 6 front-batched LDG.128 (MLP=6),
// streaming cache hints (no reuse).

__device__ __forceinline__ void lorenz_row(float yi0, float yi1, float yi2,
                                           float& o0, float& o1, float& o2) {
    const float h    = 0.01f;
    const float h2   = h * h;
    const float h3   = h2 * h;
    const float a0   = 0.5f;
    const float a1   = 1.0f / 6.0f;
    const float a2   = 1.0f / 6.0f;
    const float a4   = 3.0f / 24.0f;
    const float a5   = 1.0f / 24.0f;
    const float a6   = 1.0f / 24.0f;
    const float beta = 8.0f / 3.0f;

    const float y0 = 10.0f * yi0;
    const float y1 = 10.0f * yi1;
    const float y2 = 10.0f * yi2;

    // f(y)
    const float f0 = 10.0f * y1 - 10.0f * y0;
    const float f1 = 28.0f * y0 - y0 * y2 - y1;
    const float f2 = y0 * y1 - beta * y2;

    const float c10 = 28.0f - y2;

    // dff = jac(f)
    const float dff0 = -10.0f * f0 + 10.0f * f1;
    const float dff1 = c10 * f0 - f1 - y0 * f2;
    const float dff2 = y1 * f0 + y0 * f1 - beta * f2;

    // dfdff = jac(dff)
    const float dfdff0 = -10.0f * dff0 + 10.0f * dff1;
    const float dfdff1 = c10 * dff0 - dff1 - y0 * dff2;
    const float dfdff2 = y1 * dff0 + y0 * dff1 - beta * dff2;

    // ddfff = (0, -2 f0 f2, 2 f0 f1)
    const float ddfff1 = -2.0f * f0 * f2;
    const float ddfff2 =  2.0f * f0 * f1;

    // ddfdfff = (0, -dff0*f2 - dff2*f0, dff0*f1 + dff1*f0)
    const float ddfdfff1 = -dff0 * f2 - dff2 * f0;
    const float ddfdfff2 =  dff0 * f1 + dff1 * f0;

    // dfddfff (reference keeps its y0*f1 quirk in comp 2)
    const float dfddfff0 = 10.0f * ddfff1;
    const float dfddfff1 = -ddfff1 - y0 * ddfff2;
    const float dfddfff2 = y0 * f1 - beta * ddfff2;

    // dfdfdff = jac(dfdff)
    const float dfdfdff0 = -10.0f * dfdff0 + 10.0f * dfdff1;
    const float dfdfdff1 = c10 * dfdff0 - dfdff1 - y0 * dfdff2;
    const float dfdfdff2 = y1 * dfdff0 + y0 * dfdff1 - beta * dfdff2;

    const float c0 = f0 + a0 * h * dff0
                        + a2 * h2 * dfdff0
                        + a5 * h3 * dfddfff0
                        + a6 * h3 * dfdfdff0;
    const float c1 = f1 + a0 * h * dff1
                        + a1 * h2 * ddfff1
                        + a2 * h2 * dfdff1
                        + a4 * h3 * ddfdfff1
                        + a5 * h3 * dfddfff1
                        + a6 * h3 * dfdfdff1;
    const float c2 = f2 + a0 * h * dff2
                        + a1 * h2 * ddfff2
                        + a2 * h2 * dfdff2
                        + a4 * h3 * ddfdfff2
                        + a5 * h3 * dfddfff2
                        + a6 * h3 * dfdfdff2;

    o0 = c0 * 0.1f;
    o1 = c1 * 0.1f;
    o2 = c2 * 0.1f;
}

// Each thread handles 8 rows = 24 floats = 6 float4.
// All 6 loads are issued before any compute (MLP=6), streaming hints.
__global__ void __launch_bounds__(256)
lorenz_kernel8(const float4* __restrict__ in, float4* __restrict__ out, int n_oct) {
    const int t = blockIdx.x * blockDim.x + threadIdx.x;
    if (t >= n_oct) return;

    const int base = t * 6;

    // Front-batch all 6 128-bit loads for maximum MLP.
    float4 v0 = __ldcs(&in[base + 0]);
    float4 v1 = __ldcs(&in[base + 1]);
    float4 v2 = __ldcs(&in[base + 2]);
    float4 v3 = __ldcs(&in[base + 3]);
    float4 v4 = __ldcs(&in[base + 4]);
    float4 v5 = __ldcs(&in[base + 5]);

    float o[24];
    // rows from v0..v2
    lorenz_row(v0.x, v0.y, v0.z, o[0],  o[1],  o[2]);
    lorenz_row(v0.w, v1.x, v1.y, o[3],  o[4],  o[5]);
    lorenz_row(v1.z, v1.w, v2.x, o[6],  o[7],  o[8]);
    lorenz_row(v2.y, v2.z, v2.w, o[9],  o[10], o[11]);
    // rows from v3..v5
    lorenz_row(v3.x, v3.y, v3.z, o[12], o[13], o[14]);
    lorenz_row(v3.w, v4.x, v4.y, o[15], o[16], o[17]);
    lorenz_row(v4.z, v4.w, v5.x, o[18], o[19], o[20]);
    lorenz_row(v5.y, v5.z, v5.w, o[21], o[22], o[23]);

    __stcs(&out[base + 0], make_float4(o[0],  o[1],  o[2],  o[3]));
    __stcs(&out[base + 1], make_float4(o[4],  o[5],  o[6],  o[7]));
    __stcs(&out[base + 2], make_float4(o[8],  o[9],  o[10], o[11]));
    __stcs(&out[base + 3], make_float4(o[12], o[13], o[14], o[15]));
    __stcs(&out[base + 4], make_float4(o[16], o[17], o[18], o[19]));
    __stcs(&out[base + 5], make_float4(o[20], o[21], o[22], o[23]));
}

extern "C" void kernel_launch(void* const* d_in, const int* in_sizes, int n_in,
                              void* d_out, int out_size) {
    const float* y = (const float*)d_in[0];
    float* out = (float*)d_out;

    const long long n_elems = in_sizes[0];      // N * 3
    const long long n_rows  = n_elems / 3;      // N = 4194304
    const int n_oct = (int)(n_rows / 8);        // 8 rows per thread (N divisible by 8)

    const int threads = 256;
    const int blocks = (n_oct + threads - 1) / threads;
    lorenz_kernel8<<<blocks, threads>>>((const float4*)y, (float4*)out, n_oct);
}

// round 3
// speedup vs baseline: 1.1098x; 1.1098x over previous
#include <cuda_runtime.h>

// Lorenz Taylor-step elementwise map.  (N,3) f32 -> (N,3) f32.
// Persistent-style grid-stride with register double-buffer prefetch:
// next iteration's 3x LDG.128 are in flight while current iteration computes.

__device__ __forceinline__ void lorenz_row(float yi0, float yi1, float yi2,
                                           float& o0, float& o1, float& o2) {
    const float h    = 0.01f;
    const float h2   = h * h;
    const float h3   = h2 * h;
    const float a0   = 0.5f;
    const float a1   = 1.0f / 6.0f;
    const float a2   = 1.0f / 6.0f;
    const float a4   = 3.0f / 24.0f;
    const float a5   = 1.0f / 24.0f;
    const float a6   = 1.0f / 24.0f;
    const float beta = 8.0f / 3.0f;

    const float y0 = 10.0f * yi0;
    const float y1 = 10.0f * yi1;
    const float y2 = 10.0f * yi2;

    // f(y)
    const float f0 = 10.0f * y1 - 10.0f * y0;
    const float f1 = 28.0f * y0 - y0 * y2 - y1;
    const float f2 = y0 * y1 - beta * y2;

    const float c10 = 28.0f - y2;

    // dff = jac(f)
    const float dff0 = -10.0f * f0 + 10.0f * f1;
    const float dff1 = c10 * f0 - f1 - y0 * f2;
    const float dff2 = y1 * f0 + y0 * f1 - beta * f2;

    // dfdff = jac(dff)
    const float dfdff0 = -10.0f * dff0 + 10.0f * dff1;
    const float dfdff1 = c10 * dff0 - dff1 - y0 * dff2;
    const float dfdff2 = y1 * dff0 + y0 * dff1 - beta * dff2;

    // ddfff = (0, -2 f0 f2, 2 f0 f1)
    const float ddfff1 = -2.0f * f0 * f2;
    const float ddfff2 =  2.0f * f0 * f1;

    // ddfdfff = (0, -dff0*f2 - dff2*f0, dff0*f1 + dff1*f0)
    const float ddfdfff1 = -dff0 * f2 - dff2 * f0;
    const float ddfdfff2 =  dff0 * f1 + dff1 * f0;

    // dfddfff (reference keeps its y0*f1 quirk in comp 2)
    const float dfddfff0 = 10.0f * ddfff1;
    const float dfddfff1 = -ddfff1 - y0 * ddfff2;
    const float dfddfff2 = y0 * f1 - beta * ddfff2;

    // dfdfdff = jac(dfdff)
    const float dfdfdff0 = -10.0f * dfdff0 + 10.0f * dfdff1;
    const float dfdfdff1 = c10 * dfdff0 - dfdff1 - y0 * dfdff2;
    const float dfdfdff2 = y1 * dfdff0 + y0 * dfdff1 - beta * dfdff2;

    const float c0 = f0 + a0 * h * dff0
                        + a2 * h2 * dfdff0
                        + a5 * h3 * dfddfff0
                        + a6 * h3 * dfdfdff0;
    const float c1 = f1 + a0 * h * dff1
                        + a1 * h2 * ddfff1
                        + a2 * h2 * dfdff1
                        + a4 * h3 * ddfdfff1
                        + a5 * h3 * dfddfff1
                        + a6 * h3 * dfdfdff1;
    const float c2 = f2 + a0 * h * dff2
                        + a1 * h2 * ddfff2
                        + a2 * h2 * dfdff2
                        + a4 * h3 * ddfdfff2
                        + a5 * h3 * dfddfff2
                        + a6 * h3 * dfdfdff2;

    o0 = c0 * 0.1f;
    o1 = c1 * 0.1f;
    o2 = c2 * 0.1f;
}

__device__ __forceinline__ void do_quad(const float4& v0, const float4& v1, const float4& v2,
                                        float4& w0, float4& w1, float4& w2) {
    float o[12];
    lorenz_row(v0.x, v0.y, v0.z, o[0],  o[1],  o[2]);
    lorenz_row(v0.w, v1.x, v1.y, o[3],  o[4],  o[5]);
    lorenz_row(v1.z, v1.w, v2.x, o[6],  o[7],  o[8]);
    lorenz_row(v2.y, v2.z, v2.w, o[9],  o[10], o[11]);
    w0 = make_float4(o[0], o[1], o[2],  o[3]);
    w1 = make_float4(o[4], o[5], o[6],  o[7]);
    w2 = make_float4(o[8], o[9], o[10], o[11]);
}

// Grid-stride pipeline: each thread handles 4 rows (3 float4) per iteration,
// with the next iteration's loads issued before computing the current one.
__global__ void __launch_bounds__(256, 5)
lorenz_pipe(const float4* __restrict__ in, float4* __restrict__ out, int n_quads) {
    int i = blockIdx.x * blockDim.x + threadIdx.x;
    const int stride = gridDim.x * blockDim.x;

    if (i >= n_quads) return;

    int b = i * 3;
    float4 c0 = in[b + 0];
    float4 c1 = in[b + 1];
    float4 c2 = in[b + 2];

    for (;;) {
        const int inext = i + stride;
        const bool vnext = inext < n_quads;

        // Prefetch next iteration (in flight during compute below).
        float4 p0, p1, p2;
        int bn = inext * 3;
        if (vnext) {
            p0 = in[bn + 0];
            p1 = in[bn + 1];
            p2 = in[bn + 2];
        }

        float4 w0, w1, w2;
        do_quad(c0, c1, c2, w0, w1, w2);
        out[b + 0] = w0;
        out[b + 1] = w1;
        out[b + 2] = w2;

        if (!vnext) break;
        c0 = p0; c1 = p1; c2 = p2;
        i = inext; b = bn;
    }
}

extern "C" void kernel_launch(void* const* d_in, const int* in_sizes, int n_in,
                              void* d_out, int out_size) {
    const float* y = (const float*)d_in[0];
    float* out = (float*)d_out;

    const long long n_elems = in_sizes[0];      // N * 3
    const long long n_rows  = n_elems / 3;      // N = 4194304
    const int n_quads = (int)(n_rows / 4);      // 1,048,576 quads of 4 rows

    // Exactly-resident single wave: 5 CTAs/SM x 148 SMs.
    const int threads = 256;
    const int blocks = 5 * 148;                 // 740 CTAs, ~5.5 iters/thread
    lorenz_pipe<<<blocks, threads>>>((const float4*)y, (float4*)out, n_quads);
}